// round 6
// baseline (speedup 1.0000x reference)
#include <cuda_runtime.h>
#include <cuda_fp16.h>
#include <cuda_bf16.h>
#include <math.h>

// ---------------------------------------------------------------------------
// GraphSAGE (3x SAGEConv mean + ReLU, softmax) on GB300 — round 6.
//  * All GEMM A operands pre-split (hi|lo fp16): X split once by xsplit_kernel,
//    hidden activations split by the aggregation epilogue.
//  * GEMM: 2-stage cp.async double-buffered A pipeline; MMA overlaps loads.
//  * Split-fp16 mma.sync m16n8k16 (Ah*Wh + Al*Wh + Ah*Wl), fp32 accum.
//  * P fp16; CSR build overlapped on side stream.
// ---------------------------------------------------------------------------

#define MAXN 100000
#define MAXE 1600000

__device__ int    g_deg[MAXN];
__device__ int    g_rowptr[MAXN + 1];
__device__ int    g_cursor[MAXN];
__device__ int    g_colidx[MAXE];
__device__ float  g_invdeg[MAXN];
__device__ float  g_S[(size_t)MAXN * 128];       // self-projection (+bias), fp32
__device__ __half g_P[(size_t)MAXN * 128];       // neighbor-projection, fp16
__device__ __half g_hsplit[(size_t)MAXN * 256];  // hidden / X, (hi|lo) split fp16

static __device__ __forceinline__ unsigned su32(const void* p) {
    return (unsigned)__cvta_generic_to_shared(p);
}

#define LDSM_X4(r, a)                                                          \
    asm volatile("ldmatrix.sync.aligned.m8n8.x4.shared.b16 {%0,%1,%2,%3}, [%4];" \
                 : "=r"((r)[0]), "=r"((r)[1]), "=r"((r)[2]), "=r"((r)[3]) : "r"(a))

#define LDSM_X4T(r, a)                                                         \
    asm volatile("ldmatrix.sync.aligned.m8n8.x4.trans.shared.b16 {%0,%1,%2,%3}, [%4];" \
                 : "=r"((r)[0]), "=r"((r)[1]), "=r"((r)[2]), "=r"((r)[3]) : "r"(a))

#define MMA16816(d, a, b0, b1)                                                 \
    asm volatile("mma.sync.aligned.m16n8k16.row.col.f32.f16.f16.f32 "          \
                 "{%0,%1,%2,%3}, {%4,%5,%6,%7}, {%8,%9}, {%0,%1,%2,%3};"       \
                 : "+f"((d)[0]), "+f"((d)[1]), "+f"((d)[2]), "+f"((d)[3])      \
                 : "r"((a)[0]), "r"((a)[1]), "r"((a)[2]), "r"((a)[3]),         \
                   "r"(b0), "r"(b1))

#define CP16(dst, src, pbyte)                                                  \
    asm volatile("cp.async.cg.shared.global [%0], [%1], 16, %2;"               \
                 :: "r"(dst), "l"(src), "r"(pbyte))
#define CP_COMMIT() asm volatile("cp.async.commit_group;")
#define CP_WAIT0()  asm volatile("cp.async.wait_group 0;")

// ---------------------------- CSR construction ----------------------------

__global__ void count_deg_kernel(const int* __restrict__ dst, int* __restrict__ deg, int E) {
    int e = blockIdx.x * blockDim.x + threadIdx.x;
    if (e < E) atomicAdd(&deg[__ldg(&dst[e])], 1);
}

__global__ void scan_deg_kernel(const int* __restrict__ deg, int* __restrict__ rowptr,
                                int* __restrict__ cursor, float* __restrict__ invdeg, int n) {
    __shared__ int ssum[1024];
    int tid = threadIdx.x;
    int chunk = (n + 1023) / 1024;
    int lo = tid * chunk;
    int hi = lo + chunk; if (hi > n) hi = n;
    if (lo > n) lo = n;

    int sum = 0;
    for (int i = lo; i < hi; ++i) sum += deg[i];
    ssum[tid] = sum;
    __syncthreads();
    for (int off = 1; off < 1024; off <<= 1) {
        int v = (tid >= off) ? ssum[tid - off] : 0;
        __syncthreads();
        ssum[tid] += v;
        __syncthreads();
    }
    int run = ssum[tid] - sum;  // exclusive prefix
    for (int i = lo; i < hi; ++i) {
        rowptr[i] = run;
        cursor[i] = run;
        float d = (float)deg[i];
        invdeg[i] = 1.0f / fmaxf(d, 1.0f);
        run += deg[i];
    }
    if (tid == 1023) rowptr[n] = ssum[1023];
}

__global__ void fill_csr_kernel(const int* __restrict__ src, const int* __restrict__ dst,
                                int* __restrict__ cursor, int* __restrict__ colidx, int E) {
    int e = blockIdx.x * blockDim.x + threadIdx.x;
    if (e < E) {
        int d = __ldg(&dst[e]);
        int p = atomicAdd(&cursor[d], 1);
        colidx[p] = __ldg(&src[e]);
    }
}

// ------------------------- X pre-split (fp32 -> hi|lo fp16) ----------------

__global__ void xsplit_kernel(const float* __restrict__ X, __half* __restrict__ Y, int n) {
    int idx = blockIdx.x * blockDim.x + threadIdx.x;   // one float4 per thread
    int total = n * 32;                                 // 128 floats = 32 float4 per row
    if (idx >= total) return;
    int r = idx >> 5, c = idx & 31;
    float4 v = __ldg((const float4*)(X + (size_t)r * 128) + c);
    __half h0 = __float2half_rn(v.x), h1 = __float2half_rn(v.y);
    __half h2 = __float2half_rn(v.z), h3 = __float2half_rn(v.w);
    __half l0 = __float2half_rn(v.x - __half2float(h0));
    __half l1 = __float2half_rn(v.y - __half2float(h1));
    __half l2 = __float2half_rn(v.z - __half2float(h2));
    __half l3 = __float2half_rn(v.w - __half2float(h3));
    __half2 hA = __halves2half2(h0, h1), hB = __halves2half2(h2, h3);
    __half2 lA = __halves2half2(l0, l1), lB = __halves2half2(l2, l3);
    __half* Yr = Y + (size_t)r * 256;
    *(uint2*)(Yr + c * 4)       = make_uint2(*(unsigned*)&hA, *(unsigned*)&hB);
    *(uint2*)(Yr + 128 + c * 4) = make_uint2(*(unsigned*)&lA, *(unsigned*)&lB);
}

// ------------------- aggregation (mean) with fused epilogue ----------------
// warp per node. t = S[i] + mean_{j in N(i)} P[j]  (P fp16, fp32 accumulate)
// ACT 0: Y = relu(t) stored as (hi|lo) fp16 split, row width 2D.
// ACT 1: Y = softmax(t) stored fp32, row width D (D==64 only).

template <int D, int ACT>
__global__ void aggregate_ep(const __half* __restrict__ P, const float* __restrict__ S,
                             const int* __restrict__ rowptr, const int* __restrict__ colidx,
                             const float* __restrict__ invdeg, void* __restrict__ Yv, int n) {
    int warp = (blockIdx.x * blockDim.x + threadIdx.x) >> 5;
    int lane = threadIdx.x & 31;
    int nwarps = (gridDim.x * blockDim.x) >> 5;

    for (int i = warp; i < n; i += nwarps) {
        int s = __ldg(&rowptr[i]);
        int e = __ldg(&rowptr[i + 1]);
        float inv = __ldg(&invdeg[i]);

        if (D == 128) {
            float4 acc = make_float4(0.f, 0.f, 0.f, 0.f);
            int j = s;
            for (; j + 7 < e; j += 8) {
                int c[8];
#pragma unroll
                for (int q = 0; q < 8; ++q) c[q] = __ldg(&colidx[j + q]);
#pragma unroll
                for (int q = 0; q < 8; ++q) {
                    uint2 u = __ldg((const uint2*)(P + (size_t)c[q] * 128) + lane);
                    float2 a = __half22float2(*(const __half2*)&u.x);
                    float2 b = __half22float2(*(const __half2*)&u.y);
                    acc.x += a.x; acc.y += a.y; acc.z += b.x; acc.w += b.y;
                }
            }
            for (; j < e; ++j) {
                int c0 = __ldg(&colidx[j]);
                uint2 u = __ldg((const uint2*)(P + (size_t)c0 * 128) + lane);
                float2 a = __half22float2(*(const __half2*)&u.x);
                float2 b = __half22float2(*(const __half2*)&u.y);
                acc.x += a.x; acc.y += a.y; acc.z += b.x; acc.w += b.y;
            }
            float4 sv = __ldg((const float4*)(S + (size_t)i * 128) + lane);
            float ox = fmaxf(fmaf(acc.x, inv, sv.x), 0.f);
            float oy = fmaxf(fmaf(acc.y, inv, sv.y), 0.f);
            float oz = fmaxf(fmaf(acc.z, inv, sv.z), 0.f);
            float ow = fmaxf(fmaf(acc.w, inv, sv.w), 0.f);
            __half hx = __float2half_rn(ox), hy = __float2half_rn(oy);
            __half hz = __float2half_rn(oz), hw = __float2half_rn(ow);
            __half lx = __float2half_rn(ox - __half2float(hx));
            __half ly = __float2half_rn(oy - __half2float(hy));
            __half lz = __float2half_rn(oz - __half2float(hz));
            __half lw = __float2half_rn(ow - __half2float(hw));
            __half* Y = (__half*)Yv + (size_t)i * 256;
            __half2 hi01 = __halves2half2(hx, hy), hi23 = __halves2half2(hz, hw);
            __half2 lo01 = __halves2half2(lx, ly), lo23 = __halves2half2(lz, lw);
            *(uint2*)(Y + 4 * lane)       = make_uint2(*(unsigned*)&hi01, *(unsigned*)&hi23);
            *(uint2*)(Y + 128 + 4 * lane) = make_uint2(*(unsigned*)&lo01, *(unsigned*)&lo23);
        } else {  // D == 64
            float2 acc = make_float2(0.f, 0.f);
            int j = s;
            for (; j + 7 < e; j += 8) {
                int c[8];
#pragma unroll
                for (int q = 0; q < 8; ++q) c[q] = __ldg(&colidx[j + q]);
#pragma unroll
                for (int q = 0; q < 8; ++q) {
                    unsigned u = __ldg((const unsigned*)(P + (size_t)c[q] * 64) + lane);
                    float2 f = __half22float2(*(const __half2*)&u);
                    acc.x += f.x; acc.y += f.y;
                }
            }
            for (; j < e; ++j) {
                int c0 = __ldg(&colidx[j]);
                unsigned u = __ldg((const unsigned*)(P + (size_t)c0 * 64) + lane);
                float2 f = __half22float2(*(const __half2*)&u);
                acc.x += f.x; acc.y += f.y;
            }
            float2 sv = __ldg((const float2*)(S + (size_t)i * 64) + lane);
            float tx = fmaf(acc.x, inv, sv.x);
            float ty = fmaf(acc.y, inv, sv.y);
            if (ACT == 0) {
                float ox = fmaxf(tx, 0.f), oy = fmaxf(ty, 0.f);
                __half hx = __float2half_rn(ox), hy = __float2half_rn(oy);
                __half lx = __float2half_rn(ox - __half2float(hx));
                __half ly = __float2half_rn(oy - __half2float(hy));
                __half* Y = (__half*)Yv + (size_t)i * 128;
                __half2 hp = __halves2half2(hx, hy);
                __half2 lp = __halves2half2(lx, ly);
                *(unsigned*)(Y + 2 * lane)      = *(unsigned*)&hp;
                *(unsigned*)(Y + 64 + 2 * lane) = *(unsigned*)&lp;
            } else {
                float m = fmaxf(tx, ty);
#pragma unroll
                for (int o = 16; o; o >>= 1) m = fmaxf(m, __shfl_xor_sync(0xffffffffu, m, o));
                float ex = __expf(tx - m);
                float ey = __expf(ty - m);
                float sm = ex + ey;
#pragma unroll
                for (int o = 16; o; o >>= 1) sm += __shfl_xor_sync(0xffffffffu, sm, o);
                float rinv = 1.0f / sm;
                ((float2*)((float*)Yv + (size_t)i * 64))[lane] = make_float2(ex * rinv, ey * rinv);
            }
        }
    }
}

// ----------------------- tensor-core projection GEMM -----------------------
// A pre-split (hi|lo) fp16, row width 2K. C[64 x 128] per block-tile.
// 2-stage cp.async double buffer on sA; B (Wh|Wl) resident.
// 8 warps = 4 m-strips(16) x 2 n-halves(64).

template <int K, int MAXCTA>
__global__ __launch_bounds__(256, MAXCTA) void gemm_mma(
    const __half* __restrict__ A, const float* __restrict__ Ws,
    const float* __restrict__ Wn, const float* __restrict__ bias,
    float* __restrict__ S, __half* __restrict__ P,
    int n, int HF, int nh) {
    constexpr int LDA  = 2 * K + 8;
    constexpr int ABUF = 64 * LDA;          // halves per A buffer
    constexpr int LDB  = 136;
    constexpr int CPR  = 2 * K / 8;         // uint4 chunks per A row
    extern __shared__ __half smh[];
    __half* sA = smh;                       // [2][64][LDA]
    __half* sB = smh + 2 * ABUF;            // [2K][LDB]

    int tid = threadIdx.x;
    int h = blockIdx.x % nh;
    int colbase = h * 128;
    int t0 = blockIdx.x / nh;
    int tstep = gridDim.x / nh;

    // ---- W load + hi/lo split (once per block) ----
    for (int idx = tid; idx < K * 128; idx += 256) {
        int k = idx >> 7, c = idx & 127;
        int gc = colbase + c;
        float w = (gc < HF) ? __ldg(&Ws[k * HF + gc]) : __ldg(&Wn[k * HF + gc - HF]);
        __half wh = __float2half_rn(w);
        __half wl = __float2half_rn(w - __half2float(wh));
        sB[k * LDB + c] = wh;
        sB[(K + k) * LDB + c] = wl;
    }

    int lane = tid & 31;
    int warp = tid >> 5;
    int wm = warp & 3;
    int wnh = warp >> 2;

    int arow = wm * 16 + (lane & 15);
    int acolsel = (lane >> 4) * 8;
    int brow = lane & 15;
    int bcol = wnh * 64 + (lane >> 4) * 8;

    // A-copy assignment: CHK = 64*CPR/256 chunks per thread
    constexpr int CHK = 64 * CPR / 256;
    int cr[CHK], ccol[CHK];
#pragma unroll
    for (int q = 0; q < CHK; ++q) {
        int idx = tid + q * 256;
        cr[q] = idx / CPR;
        ccol[q] = idx % CPR;
    }

    // ---- bias init (hoisted) ----
    float2 binit[8];
#pragma unroll
    for (int nt = 0; nt < 8; ++nt) {
        int gc = colbase + wnh * 64 + nt * 8 + (lane & 3) * 2;
        float b0 = 0.f, b1 = 0.f;
        if (gc < HF) { b0 = __ldg(&bias[gc]); b1 = __ldg(&bias[gc + 1]); }
        binit[nt] = make_float2(b0, b1);
    }

    int ntiles = (n + 63) >> 6;

    // ---- prologue: async-load first tile into buf 0 ----
    if (t0 < ntiles) {
        int row0g = t0 * 64;
#pragma unroll
        for (int q = 0; q < CHK; ++q) {
            int gr = row0g + cr[q];
            unsigned d = su32(&sA[cr[q] * LDA + ccol[q] * 8]);
            int pb = (gr < n) ? 16 : 0;
            CP16(d, A + (size_t)gr * 2 * K + ccol[q] * 8, pb);
        }
    }
    CP_COMMIT();

    int cnt = 0;
    for (int t = t0; t < ntiles; t += tstep, ++cnt) {
        CP_WAIT0();
        __syncthreads();   // tile t ready; all warps past previous reads

        // issue next tile into other buffer (overlaps MMAs below)
        int tn = t + tstep;
        if (tn < ntiles) {
            int row0n = tn * 64;
            __half* dst = sA + ((cnt + 1) & 1) * ABUF;
#pragma unroll
            for (int q = 0; q < CHK; ++q) {
                int gr = row0n + cr[q];
                unsigned d = su32(&dst[cr[q] * LDA + ccol[q] * 8]);
                int pb = (gr < n) ? 16 : 0;
                CP16(d, A + (size_t)gr * 2 * K + ccol[q] * 8, pb);
            }
        }
        CP_COMMIT();

        const __half* At = sA + (cnt & 1) * ABUF;

        float acc[8][4];
#pragma unroll
        for (int nt = 0; nt < 8; ++nt) {
            acc[nt][0] = binit[nt].x; acc[nt][1] = binit[nt].y;
            acc[nt][2] = binit[nt].x; acc[nt][3] = binit[nt].y;
        }

#pragma unroll
        for (int k16 = 0; k16 < K; k16 += 16) {
            unsigned ah[4], al[4];
            LDSM_X4(ah, su32(&At[arow * LDA + k16 + acolsel]));
            LDSM_X4(al, su32(&At[arow * LDA + K + k16 + acolsel]));
#pragma unroll
            for (int tt = 0; tt < 4; ++tt) {
                unsigned bh[4], bl[4];
                LDSM_X4T(bh, su32(&sB[(k16 + brow) * LDB + bcol + tt * 16]));
                MMA16816(acc[tt * 2],     ah, bh[0], bh[1]);
                MMA16816(acc[tt * 2 + 1], ah, bh[2], bh[3]);
                MMA16816(acc[tt * 2],     al, bh[0], bh[1]);
                MMA16816(acc[tt * 2 + 1], al, bh[2], bh[3]);
                LDSM_X4T(bl, su32(&sB[(K + k16 + brow) * LDB + bcol + tt * 16]));
                MMA16816(acc[tt * 2],     ah, bl[0], bl[1]);
                MMA16816(acc[tt * 2 + 1], ah, bl[2], bl[3]);
            }
        }

        // ---- epilogue: S fp32 / P fp16 ----
        int row0g = t * 64;
        int r0 = row0g + wm * 16 + (lane >> 2);
#pragma unroll
        for (int nt = 0; nt < 8; ++nt) {
            int gc = colbase + wnh * 64 + nt * 8 + (lane & 3) * 2;
            if (gc < HF) {
                if (r0 < n)
                    *(float2*)(S + (size_t)r0 * HF + gc) = make_float2(acc[nt][0], acc[nt][1]);
                if (r0 + 8 < n)
                    *(float2*)(S + (size_t)(r0 + 8) * HF + gc) = make_float2(acc[nt][2], acc[nt][3]);
            } else {
                int pc = gc - HF;
                if (r0 < n)
                    *(__half2*)(P + (size_t)r0 * HF + pc) = __floats2half2_rn(acc[nt][0], acc[nt][1]);
                if (r0 + 8 < n)
                    *(__half2*)(P + (size_t)(r0 + 8) * HF + pc) = __floats2half2_rn(acc[nt][2], acc[nt][3]);
            }
        }
    }
}

// ---------------------------------------------------------------------------

extern "C" void kernel_launch(void* const* d_in, const int* in_sizes, int n_in,
                              void* d_out, int out_size) {
    const float* x   = (const float*)d_in[0];
    const int*   src = (const int*)d_in[1];
    const int*   dst = (const int*)d_in[2];
    const float* ws1 = (const float*)d_in[3];
    const float* wn1 = (const float*)d_in[4];
    const float* b1  = (const float*)d_in[5];
    const float* ws2 = (const float*)d_in[6];
    const float* wn2 = (const float*)d_in[7];
    const float* b2  = (const float*)d_in[8];
    const float* ws3 = (const float*)d_in[9];
    const float* wn3 = (const float*)d_in[10];
    const float* b3  = (const float*)d_in[11];
    float* out = (float*)d_out;

    int N = in_sizes[0] / 128;
    int E = in_sizes[1];

    int *deg, *rowptr, *cursor, *colidx;
    float *invdeg, *Sb;
    __half *Pb, *hs;
    cudaGetSymbolAddress((void**)&deg,    g_deg);
    cudaGetSymbolAddress((void**)&rowptr, g_rowptr);
    cudaGetSymbolAddress((void**)&cursor, g_cursor);
    cudaGetSymbolAddress((void**)&colidx, g_colidx);
    cudaGetSymbolAddress((void**)&invdeg, g_invdeg);
    cudaGetSymbolAddress((void**)&Sb,     g_S);
    cudaGetSymbolAddress((void**)&Pb,     g_P);
    cudaGetSymbolAddress((void**)&hs,     g_hsplit);

    // smem: K=128 -> 2*64*264*2 + 256*136*2 = 67584+69632 = 137216
    //       K=64  -> 2*64*136*2 + 128*136*2 = 34816+34816 = 69632
    const int SMEM_K128 = 2 * 64 * (2 * 128 + 8) * 2 + 2 * 128 * 136 * 2;
    const int SMEM_K64  = 2 * 64 * (2 * 64 + 8) * 2 + 2 * 64 * 136 * 2;
    cudaFuncSetAttribute((const void*)gemm_mma<128, 1>,
                         cudaFuncAttributeMaxDynamicSharedMemorySize, SMEM_K128);
    cudaFuncSetAttribute((const void*)gemm_mma<64, 2>,
                         cudaFuncAttributeMaxDynamicSharedMemorySize, SMEM_K64);

    // side stream for CSR build, forked/joined via events (capture-safe)
    static cudaStream_t s_csr = 0;
    static cudaEvent_t e_fork = 0, e_join = 0;
    if (!s_csr) {
        cudaStreamCreateWithFlags(&s_csr, cudaStreamNonBlocking);
        cudaEventCreateWithFlags(&e_fork, cudaEventDisableTiming);
        cudaEventCreateWithFlags(&e_join, cudaEventDisableTiming);
    }

    // ---- fork: CSR build on side stream ----
    cudaEventRecord(e_fork, 0);
    cudaStreamWaitEvent(s_csr, e_fork, 0);
    cudaMemsetAsync(deg, 0, N * sizeof(int), s_csr);
    count_deg_kernel<<<(E + 255) / 256, 256, 0, s_csr>>>(dst, deg, E);
    scan_deg_kernel<<<1, 1024, 0, s_csr>>>(deg, rowptr, cursor, invdeg, N);
    fill_csr_kernel<<<(E + 255) / 256, 256, 0, s_csr>>>(src, dst, cursor, colidx, E);
    cudaEventRecord(e_join, s_csr);

    // ---- main stream: X split, then layer-1 GEMM ----
    xsplit_kernel<<<(N * 32 + 255) / 256, 256>>>(x, hs, N);
    gemm_mma<128, 1><<<296, 256, SMEM_K128>>>(hs, ws1, wn1, b1, Sb, Pb, N, 128, 2);
    cudaStreamWaitEvent(0, e_join, 0);   // join before first aggregation

    const int AGG_BLOCKS = 2048;

    // ---- layer 1: h1split = split(relu(S1 + agg(P1))) ----
    aggregate_ep<128, 0><<<AGG_BLOCKS, 256>>>(Pb, Sb, rowptr, colidx, invdeg, hs, N);
    // ---- layer 2: h1split(K=128) -> [S2(64) | P2(64)] ----
    gemm_mma<128, 1><<<148, 256, SMEM_K128>>>(hs, ws2, wn2, b2, Sb, Pb, N, 64, 1);
    aggregate_ep<64, 0><<<AGG_BLOCKS, 256>>>(Pb, Sb, rowptr, colidx, invdeg, hs, N);
    // ---- layer 3: h2split(K=64) -> [S3(64) | P3(64)] ----
    gemm_mma<64, 2><<<296, 256, SMEM_K64>>>(hs, ws3, wn3, b3, Sb, Pb, N, 64, 1);
    aggregate_ep<64, 1><<<AGG_BLOCKS, 256>>>(Pb, Sb, rowptr, colidx, invdeg, out, N);
}